// round 2
// baseline (speedup 1.0000x reference)
#include <cuda_runtime.h>

// Problem constants (fixed by the dataset)
#define NN 100000
#define EE 1600000

// Scratch (device globals — no allocation allowed)
__device__ float g_deg [NN];
__device__ float g_agg1[NN * 64];   // sum_{j->i} x_j           (layer 1, 64-wide)
__device__ float g_h   [NN * 128];  // relu(sageconv1)          (128-wide)
__device__ float g_p   [NN * 64];   // h @ W2_l^T               (projected BEFORE aggregation)
__device__ float g_hr  [NN * 64];   // h @ W2_r^T + b2
__device__ float g_agg2[NN * 64];   // sum_{j->i} p_j

__device__ __forceinline__ void red4(float* a, float4 v) {
    asm volatile("red.global.add.v4.f32 [%0], {%1,%2,%3,%4};"
                 :: "l"(a), "f"(v.x), "f"(v.y), "f"(v.z), "f"(v.w) : "memory");
}
__device__ __forceinline__ void red1(float* a, float v) {
    asm volatile("red.global.add.f32 [%0], %1;" :: "l"(a), "f"(v) : "memory");
}

// f32x2 packed-FMA helpers (Blackwell FFMA2 — PTX-only path)
__device__ __forceinline__ unsigned long long pk2(float v) {
    unsigned long long r;
    asm("mov.b64 %0, {%1, %1};" : "=l"(r) : "r"(__float_as_uint(v)));
    return r;
}
__device__ __forceinline__ unsigned long long fma2(unsigned long long a,
                                                   unsigned long long b,
                                                   unsigned long long c) {
    unsigned long long d;
    asm("fma.rn.f32x2 %0, %1, %2, %3;" : "=l"(d) : "l"(a), "l"(b), "l"(c));
    return d;
}
__device__ __forceinline__ void upk2(unsigned long long v, float& lo, float& hi) {
    unsigned int a, b;
    asm("mov.b64 {%0, %1}, %2;" : "=r"(a), "=r"(b) : "l"(v));
    lo = __uint_as_float(a);
    hi = __uint_as_float(b);
}

// ---------------------------------------------------------------- zero
__global__ void k_zero() {
    int i = blockIdx.x * blockDim.x + threadIdx.x;
    if (i < NN * 16) {
        ((float4*)g_agg1)[i] = make_float4(0.f, 0.f, 0.f, 0.f);
        ((float4*)g_agg2)[i] = make_float4(0.f, 0.f, 0.f, 0.f);
    }
    if (i < NN) g_deg[i] = 0.f;
}

// ---------------------------------------------------------------- edge pass 1: agg1 += x[src], deg += 1
__global__ void k_edge1(const int* __restrict__ ei, const float* __restrict__ x) {
    long long idx = (long long)blockIdx.x * blockDim.x + threadIdx.x;
    int e = (int)(idx >> 4);
    if (e >= EE) return;
    int lane = (int)(idx & 15);
    int s = __ldg(ei + e);
    int d = __ldg(ei + EE + e);
    float4 v = __ldg(((const float4*)x) + (long long)s * 16 + lane);
    red4(g_agg1 + (long long)d * 64 + lane * 4, v);
    if (lane == 0) red1(g_deg + d, 1.f);
}

// ---------------------------------------------------------------- edge pass 2: agg2 += p[src]
__global__ void k_edge2(const int* __restrict__ ei) {
    long long idx = (long long)blockIdx.x * blockDim.x + threadIdx.x;
    int e = (int)(idx >> 4);
    if (e >= EE) return;
    int lane = (int)(idx & 15);
    int s = __ldg(ei + e);
    int d = __ldg(ei + EE + e);
    float4 v = __ldg(((const float4*)g_p) + (long long)s * 16 + lane);
    red4(g_agg2 + (long long)d * 64 + lane * 4, v);
}

// ---------------------------------------------------------------- GEMM layer 1
// h = relu( [agg1/deg ; x] @ Wcat^T + b1 ),  Wcat = [W1_l | W1_r], K=128, OC=128.
// Block: 64 nodes x 128 oc, 256 threads. Thread tile: 4 nodes x 8 oc (4 oc-pairs),
// FFMA2 with W pairs loaded directly from contiguous shared (no pack for W).
__global__ void __launch_bounds__(256) k_node1(const float* __restrict__ x,
                        const float* __restrict__ W1l,
                        const float* __restrict__ W1r,
                        const float* __restrict__ b1) {
    extern __shared__ float sm[];
    float* w_sh = sm;                 // [k=128][oc=128]  (row-contiguous, unpadded)
    float* a_sh = sm + 128 * 128;     // [node=64][k=128]
    float* b_sh = a_sh + 64 * 128;    // [128]
    int t = threadIdx.x;

    for (int idx = t; idx < 128 * 128; idx += 256) {
        int oc = idx >> 7, k = idx & 127;
        float v = (k < 64) ? W1l[oc * 64 + k] : W1r[oc * 64 + (k - 64)];
        w_sh[k * 128 + oc] = v;
    }
    if (t < 128) b_sh[t] = b1[t];

    int base = blockIdx.x * 64;
    for (int idx = t; idx < 64 * 128; idx += 256) {
        int node = idx >> 7, k = idx & 127;
        int n = base + node;
        float v = 0.f;
        if (n < NN) {
            if (k < 64) {
                float inv = 1.f / fmaxf(g_deg[n], 1.f);
                v = g_agg1[(long long)n * 64 + k] * inv;
            } else {
                v = x[(long long)n * 64 + (k - 64)];
            }
        }
        a_sh[node * 128 + k] = v;
    }
    __syncthreads();

    int cg = t & 15, ng = t >> 4;     // 16 oc-groups x 16 node-groups
    int ch8 = cg * 8;
    int nd4 = ng * 4;

    unsigned long long acc[4][4];     // [node i][oc-pair j]
#pragma unroll
    for (int i = 0; i < 4; i++)
#pragma unroll
        for (int j = 0; j < 4; j++) acc[i][j] = 0ull;

    const float* a_base = a_sh + nd4 * 128;
#pragma unroll 8
    for (int k = 0; k < 128; k++) {
        ulonglong2 wA = *(const ulonglong2*)(w_sh + k * 128 + ch8);      // pairs (oc,oc+1),(oc+2,oc+3)
        ulonglong2 wB = *(const ulonglong2*)(w_sh + k * 128 + ch8 + 4);  // pairs (oc+4..),(oc+6..)
        unsigned long long a2[4];
#pragma unroll
        for (int i = 0; i < 4; i++) a2[i] = pk2(a_base[i * 128 + k]);
#pragma unroll
        for (int i = 0; i < 4; i++) {
            acc[i][0] = fma2(a2[i], wA.x, acc[i][0]);
            acc[i][1] = fma2(a2[i], wA.y, acc[i][1]);
            acc[i][2] = fma2(a2[i], wB.x, acc[i][2]);
            acc[i][3] = fma2(a2[i], wB.y, acc[i][3]);
        }
    }

#pragma unroll
    for (int i = 0; i < 4; i++) {
        int n = base + nd4 + i;
        if (n < NN) {
            float o[8];
#pragma unroll
            for (int j = 0; j < 4; j++) upk2(acc[i][j], o[2 * j], o[2 * j + 1]);
            float4 v0, v1;
            v0.x = fmaxf(o[0] + b_sh[ch8 + 0], 0.f);
            v0.y = fmaxf(o[1] + b_sh[ch8 + 1], 0.f);
            v0.z = fmaxf(o[2] + b_sh[ch8 + 2], 0.f);
            v0.w = fmaxf(o[3] + b_sh[ch8 + 3], 0.f);
            v1.x = fmaxf(o[4] + b_sh[ch8 + 4], 0.f);
            v1.y = fmaxf(o[5] + b_sh[ch8 + 5], 0.f);
            v1.z = fmaxf(o[6] + b_sh[ch8 + 6], 0.f);
            v1.w = fmaxf(o[7] + b_sh[ch8 + 7], 0.f);
            *(float4*)(g_h + (long long)n * 128 + ch8) = v0;
            *(float4*)(g_h + (long long)n * 128 + ch8 + 4) = v1;
        }
    }
}

// ---------------------------------------------------------------- GEMM layer 2 (fused W2_l / W2_r):
// [p ; hr] = h @ [W2_l ; W2_r]^T ,  hr gets +b2.  oc<64 -> p, oc>=64 -> hr.
__global__ void __launch_bounds__(256) k_gemm2(const float* __restrict__ W2l,
                        const float* __restrict__ W2r,
                        const float* __restrict__ b2) {
    extern __shared__ float sm[];
    float* w_sh = sm;                 // [k=128][oc=128]
    float* a_sh = sm + 128 * 128;     // [node=64][k=128]
    float* b_sh = a_sh + 64 * 128;    // [64]
    int t = threadIdx.x;

    for (int idx = t; idx < 128 * 128; idx += 256) {
        int oc = idx >> 7, k = idx & 127;
        float v = (oc < 64) ? W2l[oc * 128 + k] : W2r[(oc - 64) * 128 + k];
        w_sh[k * 128 + oc] = v;
    }
    if (t < 64) b_sh[t] = b2[t];

    int base = blockIdx.x * 64;
    for (int idx = t; idx < 64 * 128; idx += 256) {
        int node = idx >> 7, k = idx & 127;
        int n = base + node;
        a_sh[node * 128 + k] = (n < NN) ? g_h[(long long)n * 128 + k] : 0.f;
    }
    __syncthreads();

    int cg = t & 15, ng = t >> 4;
    int ch8 = cg * 8;
    int nd4 = ng * 4;

    unsigned long long acc[4][4];
#pragma unroll
    for (int i = 0; i < 4; i++)
#pragma unroll
        for (int j = 0; j < 4; j++) acc[i][j] = 0ull;

    const float* a_base = a_sh + nd4 * 128;
#pragma unroll 8
    for (int k = 0; k < 128; k++) {
        ulonglong2 wA = *(const ulonglong2*)(w_sh + k * 128 + ch8);
        ulonglong2 wB = *(const ulonglong2*)(w_sh + k * 128 + ch8 + 4);
        unsigned long long a2[4];
#pragma unroll
        for (int i = 0; i < 4; i++) a2[i] = pk2(a_base[i * 128 + k]);
#pragma unroll
        for (int i = 0; i < 4; i++) {
            acc[i][0] = fma2(a2[i], wA.x, acc[i][0]);
            acc[i][1] = fma2(a2[i], wA.y, acc[i][1]);
            acc[i][2] = fma2(a2[i], wB.x, acc[i][2]);
            acc[i][3] = fma2(a2[i], wB.y, acc[i][3]);
        }
    }

#pragma unroll
    for (int i = 0; i < 4; i++) {
        int n = base + nd4 + i;
        if (n < NN) {
            float o[8];
#pragma unroll
            for (int j = 0; j < 4; j++) upk2(acc[i][j], o[2 * j], o[2 * j + 1]);
            if (ch8 < 64) {   // -> p (no bias)
                float4 v0 = make_float4(o[0], o[1], o[2], o[3]);
                float4 v1 = make_float4(o[4], o[5], o[6], o[7]);
                *(float4*)(g_p + (long long)n * 64 + ch8) = v0;
                *(float4*)(g_p + (long long)n * 64 + ch8 + 4) = v1;
            } else {          // -> hr (+b2)
                int c = ch8 - 64;
                float4 v0, v1;
                v0.x = o[0] + b_sh[c + 0];
                v0.y = o[1] + b_sh[c + 1];
                v0.z = o[2] + b_sh[c + 2];
                v0.w = o[3] + b_sh[c + 3];
                v1.x = o[4] + b_sh[c + 4];
                v1.y = o[5] + b_sh[c + 5];
                v1.z = o[6] + b_sh[c + 6];
                v1.w = o[7] + b_sh[c + 7];
                *(float4*)(g_hr + (long long)n * 64 + c) = v0;
                *(float4*)(g_hr + (long long)n * 64 + c + 4) = v1;
            }
        }
    }
}

// ---------------------------------------------------------------- epilogue: out = sigmoid(agg2/deg + hr)
__global__ void k_out(float* __restrict__ out) {
    int i = blockIdx.x * blockDim.x + threadIdx.x;
    if (i >= NN * 16) return;
    int n = i >> 4;
    float inv = 1.f / fmaxf(g_deg[n], 1.f);
    float4 a = ((const float4*)g_agg2)[i];
    float4 r = ((const float4*)g_hr)[i];
    float4 o;
    o.x = 1.f / (1.f + __expf(-(a.x * inv + r.x)));
    o.y = 1.f / (1.f + __expf(-(a.y * inv + r.y)));
    o.z = 1.f / (1.f + __expf(-(a.z * inv + r.z)));
    o.w = 1.f / (1.f + __expf(-(a.w * inv + r.w)));
    ((float4*)out)[i] = o;
}

// ----------------------------------------------------------------
extern "C" void kernel_launch(void* const* d_in, const int* in_sizes, int n_in,
                              void* d_out, int out_size) {
    const float* x   = (const float*)d_in[0];
    const int*   ei  = (const int*)  d_in[1];
    const float* W1l = (const float*)d_in[2];
    const float* W1r = (const float*)d_in[3];
    const float* b1  = (const float*)d_in[4];
    const float* W2l = (const float*)d_in[5];
    const float* W2r = (const float*)d_in[6];
    const float* b2  = (const float*)d_in[7];
    float* out = (float*)d_out;

    const int SMEM1 = (128 * 128 + 64 * 128 + 128) * 4;
    const int SMEM2 = (128 * 128 + 64 * 128 + 64) * 4;
    cudaFuncSetAttribute(k_node1, cudaFuncAttributeMaxDynamicSharedMemorySize, SMEM1);
    cudaFuncSetAttribute(k_gemm2, cudaFuncAttributeMaxDynamicSharedMemorySize, SMEM2);

    int zgrid = (NN * 16 + 255) / 256;
    int egrid = (int)(((long long)EE * 16 + 255) / 256);
    int ggrid = (NN + 63) / 64;

    k_zero <<<zgrid, 256>>>();
    k_edge1<<<egrid, 256>>>(ei, x);
    k_node1<<<ggrid, 256, SMEM1>>>(x, W1l, W1r, b1);
    k_gemm2<<<ggrid, 256, SMEM2>>>(W2l, W2r, b2);
    k_edge2<<<egrid, 256>>>(ei);
    k_out  <<<zgrid, 256>>>(out);
}

// round 12
// speedup vs baseline: 1.1850x; 1.1850x over previous
#include <cuda_runtime.h>

// Problem constants (fixed by the dataset)
#define NN 100000
#define EE 1600000

// Scratch (device globals — no allocation allowed)
__device__ float g_deg [NN];
__device__ float g_agg1[NN * 64];   // sum_{j->i} x_j           (layer 1, 64-wide)
__device__ float g_h   [NN * 128];  // relu(sageconv1)          (128-wide)
__device__ float g_p   [NN * 64];   // h @ W2_l^T               (projected BEFORE aggregation)
__device__ float g_hr  [NN * 64];   // h @ W2_r^T + b2
__device__ float g_agg2[NN * 64];   // sum_{j->i} p_j

__device__ __forceinline__ void red4(float* a, float4 v) {
    asm volatile("red.global.add.v4.f32 [%0], {%1,%2,%3,%4};"
                 :: "l"(a), "f"(v.x), "f"(v.y), "f"(v.z), "f"(v.w) : "memory");
}
__device__ __forceinline__ void red1(float* a, float v) {
    asm volatile("red.global.add.f32 [%0], %1;" :: "l"(a), "f"(v) : "memory");
}

// f32x2 packed-FMA helpers (Blackwell FFMA2 — PTX-only path)
__device__ __forceinline__ unsigned long long pk2(float v) {
    unsigned long long r;
    asm("mov.b64 %0, {%1, %1};" : "=l"(r) : "r"(__float_as_uint(v)));
    return r;
}
__device__ __forceinline__ unsigned long long fma2(unsigned long long a,
                                                   unsigned long long b,
                                                   unsigned long long c) {
    unsigned long long d;
    asm("fma.rn.f32x2 %0, %1, %2, %3;" : "=l"(d) : "l"(a), "l"(b), "l"(c));
    return d;
}
__device__ __forceinline__ void upk2(unsigned long long v, float& lo, float& hi) {
    unsigned int a, b;
    asm("mov.b64 {%0, %1}, %2;" : "=r"(a), "=r"(b) : "l"(v));
    lo = __uint_as_float(a);
    hi = __uint_as_float(b);
}

// ---------------------------------------------------------------- zero
__global__ void k_zero() {
    int i = blockIdx.x * blockDim.x + threadIdx.x;
    if (i < NN * 16) {
        ((float4*)g_agg1)[i] = make_float4(0.f, 0.f, 0.f, 0.f);
        ((float4*)g_agg2)[i] = make_float4(0.f, 0.f, 0.f, 0.f);
    }
    if (i < NN) g_deg[i] = 0.f;
}

// ---------------------------------------------------------------- edge pass 1: agg1 += x[src], deg += 1
__global__ void k_edge1(const int* __restrict__ ei, const float* __restrict__ x) {
    long long idx = (long long)blockIdx.x * blockDim.x + threadIdx.x;
    int e = (int)(idx >> 4);
    if (e >= EE) return;
    int lane = (int)(idx & 15);
    int s = __ldg(ei + e);
    int d = __ldg(ei + EE + e);
    float4 v = __ldg(((const float4*)x) + (long long)s * 16 + lane);
    red4(g_agg1 + (long long)d * 64 + lane * 4, v);
    if (lane == 0) red1(g_deg + d, 1.f);
}

// ---------------------------------------------------------------- edge pass 2: agg2 += p[src]
__global__ void k_edge2(const int* __restrict__ ei) {
    long long idx = (long long)blockIdx.x * blockDim.x + threadIdx.x;
    int e = (int)(idx >> 4);
    if (e >= EE) return;
    int lane = (int)(idx & 15);
    int s = __ldg(ei + e);
    int d = __ldg(ei + EE + e);
    float4 v = __ldg(((const float4*)g_p) + (long long)s * 16 + lane);
    red4(g_agg2 + (long long)d * 64 + lane * 4, v);
}

// ---------------------------------------------------------------- GEMM cores
// Block tile: 64 nodes x 128 oc, 256 threads.
// Thread (cg = t&15, ng = t>>4): 4 nodes (ng*4..+3) x 4 oc-PAIRS {cg, cg+16, cg+32, cg+48}.
// W pair loads are LDS.64 at stride 8B across cg -> conflict-free (128B/phase, banks 2cg,2cg+1).
// A loads are float2 over (k,k+1), broadcast across cg.

// GEMM layer 1: h = relu( [agg1/deg ; x] @ [W1_l|W1_r]^T + b1 )
__global__ void __launch_bounds__(256) k_node1(const float* __restrict__ x,
                        const float* __restrict__ W1l,
                        const float* __restrict__ W1r,
                        const float* __restrict__ b1) {
    extern __shared__ float sm[];
    float* w_sh = sm;                 // [k=128][oc=128]
    float* a_sh = sm + 128 * 128;     // [node=64][k=128]
    float* b_sh = a_sh + 64 * 128;    // [128]
    int t = threadIdx.x;

    for (int idx = t; idx < 128 * 128; idx += 256) {
        int oc = idx >> 7, k = idx & 127;
        float v = (k < 64) ? W1l[oc * 64 + k] : W1r[oc * 64 + (k - 64)];
        w_sh[k * 128 + oc] = v;
    }
    if (t < 128) b_sh[t] = b1[t];

    int base = blockIdx.x * 64;
    for (int idx = t; idx < 64 * 128; idx += 256) {
        int node = idx >> 7, k = idx & 127;
        int n = base + node;
        float v = 0.f;
        if (n < NN) {
            if (k < 64) {
                float inv = 1.f / fmaxf(g_deg[n], 1.f);
                v = g_agg1[(long long)n * 64 + k] * inv;
            } else {
                v = x[(long long)n * 64 + (k - 64)];
            }
        }
        a_sh[node * 128 + k] = v;
    }
    __syncthreads();

    int cg = t & 15, ng = t >> 4;
    int nd4 = ng * 4;

    unsigned long long acc[4][4];     // [node i][pair j], pair j -> oc {2cg+32j, 2cg+32j+1}
#pragma unroll
    for (int i = 0; i < 4; i++)
#pragma unroll
        for (int j = 0; j < 4; j++) acc[i][j] = 0ull;

    const float* a_base = a_sh + nd4 * 128;
#pragma unroll 4
    for (int k2 = 0; k2 < 64; k2++) {
        float2 av[4];
#pragma unroll
        for (int i = 0; i < 4; i++) av[i] = *(const float2*)(a_base + i * 128 + 2 * k2);
#pragma unroll
        for (int kk = 0; kk < 2; kk++) {
            int k = 2 * k2 + kk;
            const float* wrow = w_sh + k * 128 + 2 * cg;
            unsigned long long w0 = *(const unsigned long long*)(wrow);
            unsigned long long w1 = *(const unsigned long long*)(wrow + 32);
            unsigned long long w2 = *(const unsigned long long*)(wrow + 64);
            unsigned long long w3 = *(const unsigned long long*)(wrow + 96);
            unsigned long long a2[4];
#pragma unroll
            for (int i = 0; i < 4; i++) a2[i] = pk2(kk ? av[i].y : av[i].x);
#pragma unroll
            for (int i = 0; i < 4; i++) {
                acc[i][0] = fma2(a2[i], w0, acc[i][0]);
                acc[i][1] = fma2(a2[i], w1, acc[i][1]);
                acc[i][2] = fma2(a2[i], w2, acc[i][2]);
                acc[i][3] = fma2(a2[i], w3, acc[i][3]);
            }
        }
    }

#pragma unroll
    for (int i = 0; i < 4; i++) {
        int n = base + nd4 + i;
        if (n < NN) {
#pragma unroll
            for (int j = 0; j < 4; j++) {
                int oc = 2 * cg + 32 * j;
                float lo, hi;
                upk2(acc[i][j], lo, hi);
                float2 o;
                o.x = fmaxf(lo + b_sh[oc],     0.f);
                o.y = fmaxf(hi + b_sh[oc + 1], 0.f);
                *(float2*)(g_h + (long long)n * 128 + oc) = o;
            }
        }
    }
}

// GEMM layer 2 (fused): [p ; hr] = h @ [W2_l ; W2_r]^T, hr gets +b2.
__global__ void __launch_bounds__(256) k_gemm2(const float* __restrict__ W2l,
                        const float* __restrict__ W2r,
                        const float* __restrict__ b2) {
    extern __shared__ float sm[];
    float* w_sh = sm;                 // [k=128][oc=128]
    float* a_sh = sm + 128 * 128;     // [node=64][k=128]
    float* b_sh = a_sh + 64 * 128;    // [64]
    int t = threadIdx.x;

    for (int idx = t; idx < 128 * 128; idx += 256) {
        int oc = idx >> 7, k = idx & 127;
        float v = (oc < 64) ? W2l[oc * 128 + k] : W2r[(oc - 64) * 128 + k];
        w_sh[k * 128 + oc] = v;
    }
    if (t < 64) b_sh[t] = b2[t];

    int base = blockIdx.x * 64;
    for (int idx = t; idx < 64 * 128; idx += 256) {
        int node = idx >> 7, k = idx & 127;
        int n = base + node;
        a_sh[node * 128 + k] = (n < NN) ? g_h[(long long)n * 128 + k] : 0.f;
    }
    __syncthreads();

    int cg = t & 15, ng = t >> 4;
    int nd4 = ng * 4;

    unsigned long long acc[4][4];
#pragma unroll
    for (int i = 0; i < 4; i++)
#pragma unroll
        for (int j = 0; j < 4; j++) acc[i][j] = 0ull;

    const float* a_base = a_sh + nd4 * 128;
#pragma unroll 4
    for (int k2 = 0; k2 < 64; k2++) {
        float2 av[4];
#pragma unroll
        for (int i = 0; i < 4; i++) av[i] = *(const float2*)(a_base + i * 128 + 2 * k2);
#pragma unroll
        for (int kk = 0; kk < 2; kk++) {
            int k = 2 * k2 + kk;
            const float* wrow = w_sh + k * 128 + 2 * cg;
            unsigned long long w0 = *(const unsigned long long*)(wrow);
            unsigned long long w1 = *(const unsigned long long*)(wrow + 32);
            unsigned long long w2 = *(const unsigned long long*)(wrow + 64);
            unsigned long long w3 = *(const unsigned long long*)(wrow + 96);
            unsigned long long a2[4];
#pragma unroll
            for (int i = 0; i < 4; i++) a2[i] = pk2(kk ? av[i].y : av[i].x);
#pragma unroll
            for (int i = 0; i < 4; i++) {
                acc[i][0] = fma2(a2[i], w0, acc[i][0]);
                acc[i][1] = fma2(a2[i], w1, acc[i][1]);
                acc[i][2] = fma2(a2[i], w2, acc[i][2]);
                acc[i][3] = fma2(a2[i], w3, acc[i][3]);
            }
        }
    }

#pragma unroll
    for (int i = 0; i < 4; i++) {
        int n = base + nd4 + i;
        if (n < NN) {
#pragma unroll
            for (int j = 0; j < 4; j++) {
                int oc = 2 * cg + 32 * j;
                float lo, hi;
                upk2(acc[i][j], lo, hi);
                if (oc < 64) {            // -> p (no bias)
                    float2 o = make_float2(lo, hi);
                    *(float2*)(g_p + (long long)n * 64 + oc) = o;
                } else {                  // -> hr (+b2)
                    int c = oc - 64;
                    float2 o;
                    o.x = lo + b_sh[c];
                    o.y = hi + b_sh[c + 1];
                    *(float2*)(g_hr + (long long)n * 64 + c) = o;
                }
            }
        }
    }
}

// ---------------------------------------------------------------- epilogue: out = sigmoid(agg2/deg + hr)
__global__ void k_out(float* __restrict__ out) {
    int i = blockIdx.x * blockDim.x + threadIdx.x;
    if (i >= NN * 16) return;
    int n = i >> 4;
    float inv = 1.f / fmaxf(g_deg[n], 1.f);
    float4 a = ((const float4*)g_agg2)[i];
    float4 r = ((const float4*)g_hr)[i];
    float4 o;
    o.x = 1.f / (1.f + __expf(-(a.x * inv + r.x)));
    o.y = 1.f / (1.f + __expf(-(a.y * inv + r.y)));
    o.z = 1.f / (1.f + __expf(-(a.z * inv + r.z)));
    o.w = 1.f / (1.f + __expf(-(a.w * inv + r.w)));
    ((float4*)out)[i] = o;
}

// ----------------------------------------------------------------
extern "C" void kernel_launch(void* const* d_in, const int* in_sizes, int n_in,
                              void* d_out, int out_size) {
    const float* x   = (const float*)d_in[0];
    const int*   ei  = (const int*)  d_in[1];
    const float* W1l = (const float*)d_in[2];
    const float* W1r = (const float*)d_in[3];
    const float* b1  = (const float*)d_in[4];
    const float* W2l = (const float*)d_in[5];
    const float* W2r = (const float*)d_in[6];
    const float* b2  = (const float*)d_in[7];
    float* out = (float*)d_out;

    const int SMEM1 = (128 * 128 + 64 * 128 + 128) * 4;
    const int SMEM2 = (128 * 128 + 64 * 128 + 64) * 4;
    cudaFuncSetAttribute(k_node1, cudaFuncAttributeMaxDynamicSharedMemorySize, SMEM1);
    cudaFuncSetAttribute(k_gemm2, cudaFuncAttributeMaxDynamicSharedMemorySize, SMEM2);

    int zgrid = (NN * 16 + 255) / 256;
    int egrid = (int)(((long long)EE * 16 + 255) / 256);
    int ggrid = (NN + 63) / 64;

    k_zero <<<zgrid, 256>>>();
    k_edge1<<<egrid, 256>>>(ei, x);
    k_node1<<<ggrid, 256, SMEM1>>>(x, W1l, W1r, b1);
    k_gemm2<<<ggrid, 256, SMEM2>>>(W2l, W2r, b2);
    k_edge2<<<egrid, 256>>>(ei);
    k_out  <<<zgrid, 256>>>(out);
}